// round 3
// baseline (speedup 1.0000x reference)
#include <cuda_runtime.h>
#include <cuda_bf16.h>

// ---------------- problem constants ----------------
#define BB    4
#define NN    4096
#define DIM   512
#define HH    8
#define DHD   64
#define MM    256          // landmarks
#define INNER 512
#define BH    (BB*HH)      // 32
#define KK    33           // conv kernel
#define ITERS 6

// ---------------- scratch (static device memory; no allocs allowed) ----------
__device__ float g_xn  [BB*NN*DIM];
__device__ float g_q   [BH*NN*DHD];
__device__ float g_k   [BH*NN*DHD];
__device__ float g_v   [BH*NN*DHD];
__device__ float g_ql  [BH*MM*DHD];
__device__ float g_kl  [BH*MM*DHD];
__device__ float g_sim1[BH*NN*MM];   // -> a1
__device__ float g_sim3[BH*MM*NN];   // -> a3
__device__ float g_a2  [BH*MM*MM];
__device__ float g_z   [BH*MM*MM];
__device__ float g_z2  [BH*MM*MM];
__device__ float g_xz  [BH*MM*MM];
__device__ float g_w1  [BH*MM*MM];
__device__ float g_w2  [BH*MM*MM];
__device__ float g_w3  [BH*MM*MM];
__device__ float g_av  [BH*MM*DHD];
__device__ float g_t1  [BH*NN*MM];
__device__ float g_outh[BH*NN*DHD];
__device__ float g_rep [BB*NN*INNER];
__device__ int   g_scalbits[2];

// ---------------- reductions (256-thread blocks, 8 warps) ----------------
__device__ __forceinline__ float blockReduceSum256(float v, float* sh) {
    int lane = threadIdx.x & 31, wid = threadIdx.x >> 5;
    #pragma unroll
    for (int o = 16; o > 0; o >>= 1) v += __shfl_xor_sync(0xffffffffu, v, o);
    __syncthreads();
    if (lane == 0) sh[wid] = v;
    __syncthreads();
    float r = 0.f;
    #pragma unroll
    for (int i = 0; i < 8; i++) r += sh[i];
    return r;
}
__device__ __forceinline__ float blockReduceMax256(float v, float* sh) {
    int lane = threadIdx.x & 31, wid = threadIdx.x >> 5;
    #pragma unroll
    for (int o = 16; o > 0; o >>= 1) v = fmaxf(v, __shfl_xor_sync(0xffffffffu, v, o));
    __syncthreads();
    if (lane == 0) sh[wid] = v;
    __syncthreads();
    float r = -3.4e38f;
    #pragma unroll
    for (int i = 0; i < 8; i++) r = fmaxf(r, sh[i]);
    return r;
}

// ---------------- LayerNorm ----------------
__global__ void ln_kernel(const float* __restrict__ x, const float* __restrict__ w,
                          const float* __restrict__ b, float* __restrict__ o) {
    __shared__ float sh[8];
    long row = blockIdx.x;
    const float* xr = x + row * DIM;
    float v0 = xr[threadIdx.x], v1 = xr[threadIdx.x + 256];
    float s = blockReduceSum256(v0 + v1, sh);
    float mean = s * (1.f / DIM);
    float d0 = v0 - mean, d1 = v1 - mean;
    float s2 = blockReduceSum256(d0 * d0 + d1 * d1, sh);
    float rstd = rsqrtf(s2 * (1.f / DIM) + 1e-5f);
    o[row * DIM + threadIdx.x]       = d0 * rstd * w[threadIdx.x]       + b[threadIdx.x];
    o[row * DIM + threadIdx.x + 256] = d1 * rstd * w[threadIdx.x + 256] + b[threadIdx.x + 256];
}

// ---------------- generic batched SGEMM (row-major), 64x64 tiles ----------------
// C = diag*I + scale*(A@B) [+ bias[col]] [+ add[row*N+col]]
// Variadic macro so commas inside the B-load block survive the preprocessor.
#define GEMM_BODY(...)                                                               \
    int bz = blockIdx.z;                                                             \
    A  += (long)bz * sA;  Bm += (long)bz * sB;  C += (long)bz * sC;                  \
    int tx = threadIdx.x & 15, ty = threadIdx.x >> 4;                                \
    int row0 = blockIdx.y * 64, col0 = blockIdx.x * 64;                              \
    __shared__ float As[16][64];                                                     \
    __shared__ float Bs[16][64];                                                     \
    float acc[4][4] = {};                                                            \
    int tid = threadIdx.x;                                                           \
    int ar = tid >> 2, ak = (tid & 3) << 2;                                          \
    for (int k0 = 0; k0 < K; k0 += 16) {                                             \
        float4 av = *reinterpret_cast<const float4*>(A + (long)(row0 + ar) * K + k0 + ak); \
        As[ak][ar] = av.x; As[ak + 1][ar] = av.y; As[ak + 2][ar] = av.z; As[ak + 3][ar] = av.w; \
        __VA_ARGS__;                                                                 \
        __syncthreads();                                                             \
        _Pragma("unroll")                                                            \
        for (int kk = 0; kk < 16; kk++) {                                            \
            float4 a = *reinterpret_cast<const float4*>(&As[kk][ty * 4]);            \
            float4 b = *reinterpret_cast<const float4*>(&Bs[kk][tx * 4]);            \
            acc[0][0] += a.x * b.x; acc[0][1] += a.x * b.y; acc[0][2] += a.x * b.z; acc[0][3] += a.x * b.w; \
            acc[1][0] += a.y * b.x; acc[1][1] += a.y * b.y; acc[1][2] += a.y * b.z; acc[1][3] += a.y * b.w; \
            acc[2][0] += a.z * b.x; acc[2][1] += a.z * b.y; acc[2][2] += a.z * b.z; acc[2][3] += a.z * b.w; \
            acc[3][0] += a.w * b.x; acc[3][1] += a.w * b.y; acc[3][2] += a.w * b.z; acc[3][3] += a.w * b.w; \
        }                                                                            \
        __syncthreads();                                                             \
    }

__global__ void sgemm_nn(const float* __restrict__ A, const float* __restrict__ Bm,
                         float* __restrict__ C, int M, int N, int K,
                         long sA, long sB, long sC, float diag, float scale,
                         const float* __restrict__ bias, const float* __restrict__ add) {
    GEMM_BODY(
        int bk = tid >> 4; int bc = (tid & 15) << 2;
        *reinterpret_cast<float4*>(&Bs[bk][bc]) =
            *reinterpret_cast<const float4*>(Bm + (long)(k0 + bk) * N + col0 + bc);
    )
    #pragma unroll
    for (int i = 0; i < 4; i++) {
        int r = row0 + ty * 4 + i;
        #pragma unroll
        for (int j = 0; j < 4; j++) {
            int c = col0 + tx * 4 + j;
            float v = scale * acc[i][j];
            if (r == c) v += diag;
            if (bias) v += bias[c];
            if (add)  v += add[(long)r * N + c];
            C[(long)r * N + c] = v;
        }
    }
}

// C = A @ B^T, A:[M,K], B:[N,K]
__global__ void sgemm_nt(const float* __restrict__ A, const float* __restrict__ Bm,
                         float* __restrict__ C, int M, int N, int K,
                         long sA, long sB, long sC) {
    GEMM_BODY(
        int br = tid >> 2; int bk2 = (tid & 3) << 2;
        float4 bv = *reinterpret_cast<const float4*>(Bm + (long)(col0 + br) * K + k0 + bk2);
        Bs[bk2][br] = bv.x; Bs[bk2 + 1][br] = bv.y; Bs[bk2 + 2][br] = bv.z; Bs[bk2 + 3][br] = bv.w;
    )
    #pragma unroll
    for (int i = 0; i < 4; i++) {
        int r = row0 + ty * 4 + i;
        #pragma unroll
        for (int j = 0; j < 4; j++) {
            int c = col0 + tx * 4 + j;
            C[(long)r * N + c] = acc[i][j];
        }
    }
}

// QKV GEMM: A=[16384,512], W=[512,1536]; scatter epilogue into head layout.
__global__ void sgemm_qkv(const float* __restrict__ A, const float* __restrict__ Bm,
                          float* __restrict__ Q, float* __restrict__ Kp, float* __restrict__ V) {
    const int N = 3 * INNER, K = DIM;
    int tx = threadIdx.x & 15, ty = threadIdx.x >> 4;
    int row0 = blockIdx.y * 64, col0 = blockIdx.x * 64;
    __shared__ float As[16][64];
    __shared__ float Bs[16][64];
    float acc[4][4] = {};
    int tid = threadIdx.x;
    int ar = tid >> 2, ak = (tid & 3) << 2;
    for (int k0 = 0; k0 < K; k0 += 16) {
        float4 av = *reinterpret_cast<const float4*>(A + (long)(row0 + ar) * K + k0 + ak);
        As[ak][ar] = av.x; As[ak + 1][ar] = av.y; As[ak + 2][ar] = av.z; As[ak + 3][ar] = av.w;
        int bk = tid >> 4, bc = (tid & 15) << 2;
        *reinterpret_cast<float4*>(&Bs[bk][bc]) =
            *reinterpret_cast<const float4*>(Bm + (long)(k0 + bk) * N + col0 + bc);
        __syncthreads();
        #pragma unroll
        for (int kk = 0; kk < 16; kk++) {
            float4 a = *reinterpret_cast<const float4*>(&As[kk][ty * 4]);
            float4 b = *reinterpret_cast<const float4*>(&Bs[kk][tx * 4]);
            acc[0][0] += a.x * b.x; acc[0][1] += a.x * b.y; acc[0][2] += a.x * b.z; acc[0][3] += a.x * b.w;
            acc[1][0] += a.y * b.x; acc[1][1] += a.y * b.y; acc[1][2] += a.y * b.z; acc[1][3] += a.y * b.w;
            acc[2][0] += a.z * b.x; acc[2][1] += a.z * b.y; acc[2][2] += a.z * b.z; acc[2][3] += a.z * b.w;
            acc[3][0] += a.w * b.x; acc[3][1] += a.w * b.y; acc[3][2] += a.w * b.z; acc[3][3] += a.w * b.w;
        }
        __syncthreads();
    }
    #pragma unroll
    for (int i = 0; i < 4; i++) {
        int r = row0 + ty * 4 + i;
        int bb = r >> 12, nn = r & (NN - 1);
        #pragma unroll
        for (int j = 0; j < 4; j++) {
            int c = col0 + tx * 4 + j;
            int part = c / INNER, inner = c % INNER;
            int h = inner >> 6, d = inner & 63;
            float val = acc[i][j];
            long dst = ((long)((bb * HH + h) * NN + nn) << 6) + d;
            if (part == 0)      Q[dst] = val * 0.125f;   // DH^-0.5
            else if (part == 1) Kp[dst] = val;
            else                V[dst] = val;
        }
    }
}

// ---------------- landmarks: mean over blocks of 16 ----------------
__global__ void landmark_kernel(const float* __restrict__ q, const float* __restrict__ k,
                                float* __restrict__ ql, float* __restrict__ kl) {
    long idx = (long)blockIdx.x * 256 + threadIdx.x;   // BH*MM*DHD
    int d = idx & 63;
    int m = (idx >> 6) & (MM - 1);
    long bh = idx >> 14;
    long base = ((bh * NN + (long)m * 16) << 6) + d;
    float sq = 0.f, sk = 0.f;
    #pragma unroll
    for (int j = 0; j < 16; j++) { sq += q[base + (long)j * 64]; sk += k[base + (long)j * 64]; }
    ql[idx] = sq * (1.f / 16.f);
    kl[idx] = sk * (1.f / 16.f);
}

// ---------------- row softmax (register-resident) ----------------
template <int CNT>
__global__ void softmax_rows(float* __restrict__ X) {
    __shared__ float sh[8];
    long row = blockIdx.x;
    float* xr = X + row * (long)(CNT * 256);
    float loc[CNT];
    float mx = -3.4e38f;
    #pragma unroll
    for (int i = 0; i < CNT; i++) { loc[i] = xr[threadIdx.x + i * 256]; mx = fmaxf(mx, loc[i]); }
    mx = blockReduceMax256(mx, sh);
    float s = 0.f;
    #pragma unroll
    for (int i = 0; i < CNT; i++) { loc[i] = expf(loc[i] - mx); s += loc[i]; }
    s = blockReduceSum256(s, sh);
    float inv = 1.f / s;
    #pragma unroll
    for (int i = 0; i < CNT; i++) xr[threadIdx.x + i * 256] = loc[i] * inv;
}

// ---------------- pinv init ----------------
__global__ void scal_init_kernel() { g_scalbits[0] = 0; g_scalbits[1] = 0; }

__global__ void colmax_kernel(const float* __restrict__ a2) {   // max over row-sums of |a2|
    __shared__ float sh[8];
    long row = blockIdx.x;                       // BH*MM
    float v = fabsf(a2[row * MM + threadIdx.x]);
    v = blockReduceSum256(v, sh);
    if (threadIdx.x == 0) atomicMax(&g_scalbits[0], __float_as_int(v));
}
__global__ void rowmax_kernel(const float* __restrict__ a2) {   // max over col-sums of |a2|
    __shared__ float sh[8];
    long col = blockIdx.x;                       // BH*MM
    long bh = col >> 8; int j = col & (MM - 1);
    float v = fabsf(a2[(bh << 16) + (long)threadIdx.x * MM + j]);
    v = blockReduceSum256(v, sh);
    if (threadIdx.x == 0) atomicMax(&g_scalbits[1], __float_as_int(v));
}
__global__ void zinit_kernel(const float* __restrict__ a2, float* __restrict__ z) {
    long idx = (long)blockIdx.x * 256 + threadIdx.x;  // BH*MM*MM
    float denom = __int_as_float(g_scalbits[0]) * __int_as_float(g_scalbits[1]);
    long bh = idx >> 16; int i = (idx >> 8) & 255, j = idx & 255;
    z[idx] = a2[(bh << 16) + (long)j * MM + i] / denom;
}
__global__ void w1_kernel(const float* __restrict__ xz, float* __restrict__ w1) {
    long idx = (long)blockIdx.x * 256 + threadIdx.x;
    int i = (idx >> 8) & 255, j = idx & 255;
    w1[idx] = (i == j ? 7.f : 0.f) - xz[idx];
}

// ---------------- depthwise conv residual: outh += conv(v) ----------------
__global__ void conv_kernel(const float* __restrict__ v, const float* __restrict__ w,
                            float* __restrict__ outh) {
    long idx = (long)blockIdx.x * 256 + threadIdx.x;   // BH*NN*DHD
    int d = idx & 63;
    int n = (idx >> 6) & (NN - 1);
    long bh = idx >> 18;
    int h = (int)(bh & 7);
    const float* vb = v + ((bh * NN) << 6) + d;
    float s = 0.f;
    #pragma unroll
    for (int kk = 0; kk < KK; kk++) {
        int nn = n + kk - KK / 2;
        if (nn >= 0 && nn < NN) s += w[h * KK + kk] * vb[(long)nn * 64];
    }
    outh[idx] += s;
}

// ---------------- repack [B,H,N,D] -> [B,N,H*D] ----------------
__global__ void repack_kernel(const float* __restrict__ outh, float* __restrict__ rep) {
    long idx = (long)blockIdx.x * 256 + threadIdx.x;   // BB*NN*INNER
    int c = idx & (INNER - 1);
    long r = idx >> 9;
    int h = c >> 6, d = c & 63;
    long bb = r >> 12, nn = r & (NN - 1);
    rep[idx] = outh[(((bb * HH + h) * NN + nn) << 6) + d];
}

// ---------------- host ----------------
static inline void* sym(const void* s) { void* p = nullptr; cudaGetSymbolAddress(&p, s); return p; }

extern "C" void kernel_launch(void* const* d_in, const int* in_sizes, int n_in,
                              void* d_out, int out_size) {
    const float* x    = (const float*)d_in[0];
    const float* nw   = (const float*)d_in[1];
    const float* nb   = (const float*)d_in[2];
    const float* wqkv = (const float*)d_in[3];
    const float* wout = (const float*)d_in[4];
    const float* bout = (const float*)d_in[5];
    const float* resw = (const float*)d_in[6];
    float* out = (float*)d_out;

    float* xn   = (float*)sym(g_xn);
    float* q    = (float*)sym(g_q);
    float* k    = (float*)sym(g_k);
    float* v    = (float*)sym(g_v);
    float* ql   = (float*)sym(g_ql);
    float* kl   = (float*)sym(g_kl);
    float* sim1 = (float*)sym(g_sim1);
    float* sim3 = (float*)sym(g_sim3);
    float* a2   = (float*)sym(g_a2);
    float* z    = (float*)sym(g_z);
    float* z2   = (float*)sym(g_z2);
    float* xz   = (float*)sym(g_xz);
    float* w1   = (float*)sym(g_w1);
    float* w2   = (float*)sym(g_w2);
    float* w3   = (float*)sym(g_w3);
    float* av   = (float*)sym(g_av);
    float* t1   = (float*)sym(g_t1);
    float* outh = (float*)sym(g_outh);
    float* rep  = (float*)sym(g_rep);

    // 1. LayerNorm
    ln_kernel<<<BB * NN, 256>>>(x, nw, nb, xn);

    // 2. QKV projection with head-layout scatter + q scaling
    sgemm_qkv<<<dim3((3 * INNER) / 64, (BB * NN) / 64, 1), 256>>>(xn, wqkv, q, k, v);

    // 3. Landmarks
    landmark_kernel<<<(BH * MM * DHD) / 256, 256>>>(q, k, ql, kl);

    // 4. Similarities
    sgemm_nt<<<dim3(MM / 64, NN / 64, BH), 256>>>(q,  kl, sim1, NN, MM, DHD,
        (long)NN * DHD, (long)MM * DHD, (long)NN * MM);
    sgemm_nt<<<dim3(MM / 64, MM / 64, BH), 256>>>(ql, kl, a2,   MM, MM, DHD,
        (long)MM * DHD, (long)MM * DHD, (long)MM * MM);
    sgemm_nt<<<dim3(NN / 64, MM / 64, BH), 256>>>(ql, k,  sim3, MM, NN, DHD,
        (long)MM * DHD, (long)NN * DHD, (long)MM * NN);

    // 5. Softmaxes
    softmax_rows<1><<<BH * NN, 256>>>(sim1);   // rows of length 256
    softmax_rows<1><<<BH * MM, 256>>>(a2);
    softmax_rows<16><<<BH * MM, 256>>>(sim3);  // rows of length 4096

    // 6. pinv init
    scal_init_kernel<<<1, 1>>>();
    colmax_kernel<<<BH * MM, 256>>>(a2);
    rowmax_kernel<<<BH * MM, 256>>>(a2);
    zinit_kernel<<<(BH * MM * MM) / 256, 256>>>(a2, z);

    // 7. Newton-Schulz iterations
    const long sM = (long)MM * MM;
    dim3 gmm(MM / 64, MM / 64, BH);
    for (int it = 0; it < ITERS; it++) {
        float* zin  = (it & 1) ? z2 : z;
        float* zout = (it & 1) ? z  : z2;
        sgemm_nn<<<gmm, 256>>>(a2,  zin, xz, MM, MM, MM, sM, sM, sM, 0.f,  1.f,   nullptr, nullptr);
        w1_kernel<<<(BH * MM * MM) / 256, 256>>>(xz, w1);
        sgemm_nn<<<gmm, 256>>>(xz, w1, w2, MM, MM, MM, sM, sM, sM, 15.f, -1.f,  nullptr, nullptr);
        sgemm_nn<<<gmm, 256>>>(xz, w2, w3, MM, MM, MM, sM, sM, sM, 13.f, -1.f,  nullptr, nullptr);
        sgemm_nn<<<gmm, 256>>>(zin, w3, zout, MM, MM, MM, sM, sM, sM, 0.f, 0.25f, nullptr, nullptr);
    }
    // after even #iters, result in z

    // 8. out = (a1 @ z) @ (a3 @ v)
    sgemm_nn<<<dim3(DHD / 64, MM / 64, BH), 256>>>(sim3, v, av, MM, DHD, NN,
        (long)MM * NN, (long)NN * DHD, (long)MM * DHD, 0.f, 1.f, nullptr, nullptr);
    sgemm_nn<<<dim3(MM / 64, NN / 64, BH), 256>>>(sim1, z, t1, NN, MM, MM,
        (long)NN * MM, sM, (long)NN * MM, 0.f, 1.f, nullptr, nullptr);
    sgemm_nn<<<dim3(DHD / 64, NN / 64, BH), 256>>>(t1, av, outh, NN, DHD, MM,
        (long)NN * MM, (long)MM * DHD, (long)NN * DHD, 0.f, 1.f, nullptr, nullptr);

    // 9. residual depthwise conv
    conv_kernel<<<(BH * NN * DHD) / 256, 256>>>(v, resw, outh);

    // 10. repack to [B,N,INNER]
    repack_kernel<<<(BB * NN * INNER) / 256, 256>>>(outh, rep);

    // 11. out projection + bias + residual
    sgemm_nn<<<dim3(DIM / 64, (BB * NN) / 64, 1), 256>>>(rep, wout, out,
        BB * NN, DIM, INNER, 0, 0, 0, 0.f, 1.f, bout, x);

    (void)in_sizes; (void)n_in; (void)out_size;
}

// round 4
// speedup vs baseline: 1.3391x; 1.3391x over previous
#include <cuda_runtime.h>

// ---------------- problem constants ----------------
#define BB    4
#define NN    4096
#define DIM   512
#define HH    8
#define DHD   64
#define MM    256
#define INNER 512
#define BH    (BB*HH)
#define KK    33
#define ITERS 6

// ---------------- scratch ----------------
__device__ float g_xn  [BB*NN*DIM];
__device__ float g_q   [BH*NN*DHD];
__device__ float g_k   [BH*NN*DHD];
__device__ float g_v   [BH*NN*DHD];
__device__ float g_ql  [BH*MM*DHD];
__device__ float g_kl  [BH*MM*DHD];
__device__ float g_sim1[BH*NN*MM];
__device__ float g_sim3[BH*MM*NN];
__device__ float g_a2  [BH*MM*MM];
__device__ float g_z   [BH*MM*MM];
__device__ float g_z2  [BH*MM*MM];
__device__ float g_xz  [BH*MM*MM];
__device__ float g_w1  [BH*MM*MM];
__device__ float g_w2  [BH*MM*MM];
__device__ float g_w3  [BH*MM*MM];
__device__ float g_avp [BH*8*MM*DHD];
__device__ float g_av  [BH*MM*DHD];
__device__ float g_zav [BH*MM*DHD];
__device__ float g_outh[BH*NN*DHD];
__device__ float g_rep [BB*NN*INNER];
__device__ int   g_scalbits[2];

// ---------------- reductions ----------------
__device__ __forceinline__ float blockReduceSum256(float v, float* sh) {
    int lane = threadIdx.x & 31, wid = threadIdx.x >> 5;
    #pragma unroll
    for (int o = 16; o > 0; o >>= 1) v += __shfl_xor_sync(0xffffffffu, v, o);
    __syncthreads();
    if (lane == 0) sh[wid] = v;
    __syncthreads();
    float r = 0.f;
    #pragma unroll
    for (int i = 0; i < 8; i++) r += sh[i];
    return r;
}
__device__ __forceinline__ float blockReduceMax256(float v, float* sh) {
    int lane = threadIdx.x & 31, wid = threadIdx.x >> 5;
    #pragma unroll
    for (int o = 16; o > 0; o >>= 1) v = fmaxf(v, __shfl_xor_sync(0xffffffffu, v, o));
    __syncthreads();
    if (lane == 0) sh[wid] = v;
    __syncthreads();
    float r = -3.4e38f;
    #pragma unroll
    for (int i = 0; i < 8; i++) r = fmaxf(r, sh[i]);
    return r;
}

// ---------------- LayerNorm ----------------
__global__ void ln_kernel(const float* __restrict__ x, const float* __restrict__ w,
                          const float* __restrict__ b, float* __restrict__ o) {
    __shared__ float sh[8];
    long row = blockIdx.x;
    const float* xr = x + row * DIM;
    float v0 = xr[threadIdx.x], v1 = xr[threadIdx.x + 256];
    float s = blockReduceSum256(v0 + v1, sh);
    float mean = s * (1.f / DIM);
    float d0 = v0 - mean, d1 = v1 - mean;
    float s2 = blockReduceSum256(d0 * d0 + d1 * d1, sh);
    float rstd = rsqrtf(s2 * (1.f / DIM) + 1e-5f);
    o[row * DIM + threadIdx.x]       = d0 * rstd * w[threadIdx.x]       + b[threadIdx.x];
    o[row * DIM + threadIdx.x + 256] = d1 * rstd * w[threadIdx.x + 256] + b[threadIdx.x + 256];
}

// ================= 128x128-tile GEMM, 8x8 per thread =================
// C = diag*I + scale*(A@op(B)) [+bias[col]] [+add[row*ldc+col]]
// optional C2 = diag2*I - (A@op(B))       (requires scale==1 semantics for C2)
// NT=0: B row-major [K,ldb];  NT=1: B row-major [N,ldb], used transposed.
template<int NT>
__global__ __launch_bounds__(256) void gemm_w(
    const float* __restrict__ A, const float* __restrict__ B,
    float* __restrict__ C, float* __restrict__ C2,
    int K, int lda, int ldb, int ldc, long sA, long sB, long sC,
    float diag, float scale, float diag2,
    const float* __restrict__ bias, const float* __restrict__ add)
{
    int z = blockIdx.z;
    A += (long)z * sA;  B += (long)z * sB;  C += (long)z * sC;
    if (C2) C2 += (long)z * sC;
    int row0 = blockIdx.y * 128, col0 = blockIdx.x * 128;
    __shared__ float As[16][128];
    __shared__ float Bs[16][128];
    int tid = threadIdx.x, lane = tid & 31, warp = tid >> 5;
    int wr = (warp >> 1) * 32, wc = (warp & 1) * 64;
    int r4 = (lane >> 3) * 4, c4 = (lane & 7) * 4;
    int ra = wr + r4, rb = ra + 16;
    int ca = wc + c4, cb = ca + 32;
    int ar = tid >> 1, ak = (tid & 1) * 8;
    float acc[8][8] = {};
    for (int k0 = 0; k0 < K; k0 += 16) {
        float4 a0 = *(const float4*)(A + (long)(row0 + ar) * lda + k0 + ak);
        float4 a1 = *(const float4*)(A + (long)(row0 + ar) * lda + k0 + ak + 4);
        As[ak+0][ar]=a0.x; As[ak+1][ar]=a0.y; As[ak+2][ar]=a0.z; As[ak+3][ar]=a0.w;
        As[ak+4][ar]=a1.x; As[ak+5][ar]=a1.y; As[ak+6][ar]=a1.z; As[ak+7][ar]=a1.w;
        if (NT) {
            float4 b0 = *(const float4*)(B + (long)(col0 + ar) * ldb + k0 + ak);
            float4 b1 = *(const float4*)(B + (long)(col0 + ar) * ldb + k0 + ak + 4);
            Bs[ak+0][ar]=b0.x; Bs[ak+1][ar]=b0.y; Bs[ak+2][ar]=b0.z; Bs[ak+3][ar]=b0.w;
            Bs[ak+4][ar]=b1.x; Bs[ak+5][ar]=b1.y; Bs[ak+6][ar]=b1.z; Bs[ak+7][ar]=b1.w;
        } else {
            int bk = tid >> 4, bc = (tid & 15) * 8;
            *(float4*)&Bs[bk][bc]     = *(const float4*)(B + (long)(k0 + bk) * ldb + col0 + bc);
            *(float4*)&Bs[bk][bc + 4] = *(const float4*)(B + (long)(k0 + bk) * ldb + col0 + bc + 4);
        }
        __syncthreads();
        #pragma unroll
        for (int kk = 0; kk < 16; kk++) {
            float4 x0 = *(const float4*)&As[kk][ra];
            float4 x1 = *(const float4*)&As[kk][rb];
            float4 y0 = *(const float4*)&Bs[kk][ca];
            float4 y1 = *(const float4*)&Bs[kk][cb];
            float av_[8] = {x0.x,x0.y,x0.z,x0.w,x1.x,x1.y,x1.z,x1.w};
            float bv_[8] = {y0.x,y0.y,y0.z,y0.w,y1.x,y1.y,y1.z,y1.w};
            #pragma unroll
            for (int i = 0; i < 8; i++)
                #pragma unroll
                for (int j = 0; j < 8; j++) acc[i][j] += av_[i] * bv_[j];
        }
        __syncthreads();
    }
    #pragma unroll
    for (int i = 0; i < 8; i++) {
        int lrow = (i < 4) ? (ra + i) : (rb + i - 4);
        int grow = row0 + lrow;
        #pragma unroll
        for (int half = 0; half < 2; half++) {
            int lc0 = half ? cb : ca;
            int gc0 = col0 + lc0;
            float4 v; float* vp = &v.x;
            #pragma unroll
            for (int j = 0; j < 4; j++) {
                float val = scale * acc[i][half * 4 + j];
                int gcol = gc0 + j;
                if (grow == gcol) val += diag;
                if (bias) val += bias[gcol];
                if (add)  val += add[(long)grow * ldc + gcol];
                vp[j] = val;
            }
            *(float4*)(C + (long)grow * ldc + gc0) = v;
            if (C2) {
                float4 w; float* wp = &w.x;
                #pragma unroll
                for (int j = 0; j < 4; j++) {
                    float val = -acc[i][half * 4 + j];
                    if (grow == gc0 + j) val += diag2;
                    wp[j] = val;
                }
                *(float4*)(C2 + (long)grow * ldc + gc0) = w;
            }
        }
    }
}

// ---- QKV: same core, scatter epilogue into [B,H,N,D] with q scaling ----
__global__ __launch_bounds__(256) void gemm_qkv(
    const float* __restrict__ A, const float* __restrict__ B,
    float* __restrict__ Q, float* __restrict__ Kp, float* __restrict__ V)
{
    const int lda = DIM, ldb = 3 * INNER;
    int row0 = blockIdx.y * 128, col0 = blockIdx.x * 128;
    __shared__ float As[16][128];
    __shared__ float Bs[16][128];
    int tid = threadIdx.x, lane = tid & 31, warp = tid >> 5;
    int wr = (warp >> 1) * 32, wc = (warp & 1) * 64;
    int r4 = (lane >> 3) * 4, c4 = (lane & 7) * 4;
    int ra = wr + r4, rb = ra + 16;
    int ca = wc + c4, cb = ca + 32;
    int ar = tid >> 1, ak = (tid & 1) * 8;
    float acc[8][8] = {};
    for (int k0 = 0; k0 < DIM; k0 += 16) {
        float4 a0 = *(const float4*)(A + (long)(row0 + ar) * lda + k0 + ak);
        float4 a1 = *(const float4*)(A + (long)(row0 + ar) * lda + k0 + ak + 4);
        As[ak+0][ar]=a0.x; As[ak+1][ar]=a0.y; As[ak+2][ar]=a0.z; As[ak+3][ar]=a0.w;
        As[ak+4][ar]=a1.x; As[ak+5][ar]=a1.y; As[ak+6][ar]=a1.z; As[ak+7][ar]=a1.w;
        int bk = tid >> 4, bc = (tid & 15) * 8;
        *(float4*)&Bs[bk][bc]     = *(const float4*)(B + (long)(k0 + bk) * ldb + col0 + bc);
        *(float4*)&Bs[bk][bc + 4] = *(const float4*)(B + (long)(k0 + bk) * ldb + col0 + bc + 4);
        __syncthreads();
        #pragma unroll
        for (int kk = 0; kk < 16; kk++) {
            float4 x0 = *(const float4*)&As[kk][ra];
            float4 x1 = *(const float4*)&As[kk][rb];
            float4 y0 = *(const float4*)&Bs[kk][ca];
            float4 y1 = *(const float4*)&Bs[kk][cb];
            float av_[8] = {x0.x,x0.y,x0.z,x0.w,x1.x,x1.y,x1.z,x1.w};
            float bv_[8] = {y0.x,y0.y,y0.z,y0.w,y1.x,y1.y,y1.z,y1.w};
            #pragma unroll
            for (int i = 0; i < 8; i++)
                #pragma unroll
                for (int j = 0; j < 8; j++) acc[i][j] += av_[i] * bv_[j];
        }
        __syncthreads();
    }
    #pragma unroll
    for (int i = 0; i < 8; i++) {
        int grow = row0 + ((i < 4) ? (ra + i) : (rb + i - 4));
        int bb = grow >> 12, nn = grow & (NN - 1);
        #pragma unroll
        for (int j = 0; j < 8; j++) {
            int gcol = col0 + ((j < 4) ? (ca + j) : (cb + j - 4));
            int part = gcol / INNER, inner = gcol % INNER;
            int h = inner >> 6, d = inner & 63;
            long dst = ((long)((bb * HH + h) * NN + nn) << 6) + d;
            float val = acc[i][j];
            if (part == 0)      Q[dst]  = val * 0.125f;
            else if (part == 1) Kp[dst] = val;
            else                V[dst]  = val;
        }
    }
}

// ================= narrow GEMM: 128xM rows, N=64, with split-K batching ======
// z -> bh = z/CPB, ch = z%CPB; A += bh*sA + ch*chA; B += bh*sB + ch*chB; C += z*sC
__global__ __launch_bounds__(256) void gemm_n(
    const float* __restrict__ A, const float* __restrict__ B, float* __restrict__ C,
    int K, int lda, int ldb, long sA, long sB, long sC,
    int CPB, long chA, long chB, float scale)
{
    int z = blockIdx.z;
    int bh = z / CPB, ch = z - bh * CPB;
    A += (long)bh * sA + (long)ch * chA;
    B += (long)bh * sB + (long)ch * chB;
    C += (long)z * sC;
    int row0 = blockIdx.y * 128;
    __shared__ float As[16][128];
    __shared__ float Bs[16][64];
    int tid = threadIdx.x, lane = tid & 31, warp = tid >> 5;
    int ra = warp * 16 + (lane >> 3) * 4;
    int c4 = (lane & 7) * 4;
    int ar = tid >> 1, ak = (tid & 1) * 8;
    float acc[4][8] = {};
    for (int k0 = 0; k0 < K; k0 += 16) {
        float4 a0 = *(const float4*)(A + (long)(row0 + ar) * lda + k0 + ak);
        float4 a1 = *(const float4*)(A + (long)(row0 + ar) * lda + k0 + ak + 4);
        As[ak+0][ar]=a0.x; As[ak+1][ar]=a0.y; As[ak+2][ar]=a0.z; As[ak+3][ar]=a0.w;
        As[ak+4][ar]=a1.x; As[ak+5][ar]=a1.y; As[ak+6][ar]=a1.z; As[ak+7][ar]=a1.w;
        if (tid < 256) {
            int bk = tid >> 4, bc = (tid & 15) * 4;
            *(float4*)&Bs[bk][bc] = *(const float4*)(B + (long)(k0 + bk) * ldb + bc);
        }
        __syncthreads();
        #pragma unroll
        for (int kk = 0; kk < 16; kk++) {
            float4 x0 = *(const float4*)&As[kk][ra];
            float4 y0 = *(const float4*)&Bs[kk][c4];
            float4 y1 = *(const float4*)&Bs[kk][c4 + 32];
            float av_[4] = {x0.x,x0.y,x0.z,x0.w};
            float bv_[8] = {y0.x,y0.y,y0.z,y0.w,y1.x,y1.y,y1.z,y1.w};
            #pragma unroll
            for (int i = 0; i < 4; i++)
                #pragma unroll
                for (int j = 0; j < 8; j++) acc[i][j] += av_[i] * bv_[j];
        }
        __syncthreads();
    }
    #pragma unroll
    for (int i = 0; i < 4; i++) {
        int grow = row0 + ra + i;
        float4 v0, v1;
        v0.x = scale*acc[i][0]; v0.y = scale*acc[i][1]; v0.z = scale*acc[i][2]; v0.w = scale*acc[i][3];
        v1.x = scale*acc[i][4]; v1.y = scale*acc[i][5]; v1.z = scale*acc[i][6]; v1.w = scale*acc[i][7];
        *(float4*)(C + (long)grow * 64 + c4)      = v0;
        *(float4*)(C + (long)grow * 64 + c4 + 32) = v1;
    }
}

// split-K reduce for av
__global__ void avreduce_kernel(const float* __restrict__ p, float* __restrict__ o) {
    long idx = (long)blockIdx.x * 256 + threadIdx.x;  // BH*MM*DHD
    long bh = idx >> 14;
    long t = idx & 16383;
    float s = 0.f;
    #pragma unroll
    for (int c = 0; c < 8; c++) s += p[((bh * 8 + c) << 14) + t];
    o[idx] = s;
}

// ---------------- landmarks ----------------
__global__ void landmark_kernel(const float* __restrict__ q, const float* __restrict__ k,
                                float* __restrict__ ql, float* __restrict__ kl) {
    long idx = (long)blockIdx.x * 256 + threadIdx.x;
    int d = idx & 63;
    int m = (idx >> 6) & (MM - 1);
    long bh = idx >> 14;
    long base = ((bh * NN + (long)m * 16) << 6) + d;
    float sq = 0.f, sk = 0.f;
    #pragma unroll
    for (int j = 0; j < 16; j++) { sq += q[base + (long)j * 64]; sk += k[base + (long)j * 64]; }
    ql[idx] = sq * (1.f / 16.f);
    kl[idx] = sk * (1.f / 16.f);
}

// ---------------- softmax ----------------
template <int CNT>
__global__ void softmax_rows(float* __restrict__ X) {
    __shared__ float sh[8];
    long row = blockIdx.x;
    float* xr = X + row * (long)(CNT * 256);
    float loc[CNT];
    float mx = -3.4e38f;
    #pragma unroll
    for (int i = 0; i < CNT; i++) { loc[i] = xr[threadIdx.x + i * 256]; mx = fmaxf(mx, loc[i]); }
    mx = blockReduceMax256(mx, sh);
    float s = 0.f;
    #pragma unroll
    for (int i = 0; i < CNT; i++) { loc[i] = expf(loc[i] - mx); s += loc[i]; }
    s = blockReduceSum256(s, sh);
    float inv = 1.f / s;
    #pragma unroll
    for (int i = 0; i < CNT; i++) xr[threadIdx.x + i * 256] = loc[i] * inv;
}

// ---------------- pinv init ----------------
__global__ void scal_init_kernel() { g_scalbits[0] = 0; g_scalbits[1] = 0; }

__global__ void colmax_kernel(const float* __restrict__ a2) {
    __shared__ float sh[8];
    long row = blockIdx.x;
    float v = fabsf(a2[row * MM + threadIdx.x]);
    v = blockReduceSum256(v, sh);
    if (threadIdx.x == 0) atomicMax(&g_scalbits[0], __float_as_int(v));
}
__global__ void rowmax_kernel(const float* __restrict__ a2) {
    __shared__ float sh[8];
    long col = blockIdx.x;
    long bh = col >> 8; int j = col & (MM - 1);
    float v = fabsf(a2[(bh << 16) + (long)threadIdx.x * MM + j]);
    v = blockReduceSum256(v, sh);
    if (threadIdx.x == 0) atomicMax(&g_scalbits[1], __float_as_int(v));
}
__global__ void zinit_kernel(const float* __restrict__ a2, float* __restrict__ z) {
    long idx = (long)blockIdx.x * 256 + threadIdx.x;
    float denom = __int_as_float(g_scalbits[0]) * __int_as_float(g_scalbits[1]);
    long bh = idx >> 16; int i = (idx >> 8) & 255, j = idx & 255;
    z[idx] = a2[(bh << 16) + (long)j * MM + i] / denom;
}

// ---------------- depthwise conv: outh += conv(v) ----------------
__global__ void conv_kernel(const float* __restrict__ v, const float* __restrict__ w,
                            float* __restrict__ outh) {
    long idx = (long)blockIdx.x * 256 + threadIdx.x;
    int d = idx & 63;
    int n = (idx >> 6) & (NN - 1);
    long bh = idx >> 18;
    int h = (int)(bh & 7);
    const float* vb = v + ((bh * NN) << 6) + d;
    float s = 0.f;
    #pragma unroll
    for (int kk = 0; kk < KK; kk++) {
        int nn = n + kk - KK / 2;
        if (nn >= 0 && nn < NN) s += w[h * KK + kk] * vb[(long)nn * 64];
    }
    outh[idx] += s;
}

// ---------------- repack [B,H,N,D] -> [B,N,H*D] ----------------
__global__ void repack_kernel(const float* __restrict__ outh, float* __restrict__ rep) {
    long idx = (long)blockIdx.x * 256 + threadIdx.x;
    int c = idx & (INNER - 1);
    long r = idx >> 9;
    int h = c >> 6, d = c & 63;
    long bb = r >> 12, nn = r & (NN - 1);
    rep[idx] = outh[(((bb * HH + h) * NN + nn) << 6) + d];
}

// ---------------- host ----------------
static inline void* sym(const void* s) { void* p = nullptr; cudaGetSymbolAddress(&p, s); return p; }

extern "C" void kernel_launch(void* const* d_in, const int* in_sizes, int n_in,
                              void* d_out, int out_size) {
    const float* x    = (const float*)d_in[0];
    const float* nw   = (const float*)d_in[1];
    const float* nb   = (const float*)d_in[2];
    const float* wqkv = (const float*)d_in[3];
    const float* wout = (const float*)d_in[4];
    const float* bout = (const float*)d_in[5];
    const float* resw = (const float*)d_in[6];
    float* out = (float*)d_out;

    float* xn   = (float*)sym(g_xn);
    float* q    = (float*)sym(g_q);
    float* k    = (float*)sym(g_k);
    float* v    = (float*)sym(g_v);
    float* ql   = (float*)sym(g_ql);
    float* kl   = (float*)sym(g_kl);
    float* sim1 = (float*)sym(g_sim1);
    float* sim3 = (float*)sym(g_sim3);
    float* a2   = (float*)sym(g_a2);
    float* z    = (float*)sym(g_z);
    float* z2   = (float*)sym(g_z2);
    float* xz   = (float*)sym(g_xz);
    float* w1   = (float*)sym(g_w1);
    float* w2   = (float*)sym(g_w2);
    float* w3   = (float*)sym(g_w3);
    float* avp  = (float*)sym(g_avp);
    float* av   = (float*)sym(g_av);
    float* zav  = (float*)sym(g_zav);
    float* outh = (float*)sym(g_outh);
    float* rep  = (float*)sym(g_rep);

    const long sMM = (long)MM * MM;

    // 1. LayerNorm
    ln_kernel<<<BB * NN, 256>>>(x, nw, nb, xn);

    // 2. QKV projection (scatter to head layout, q pre-scaled)
    gemm_qkv<<<dim3(12, 128, 1), 256>>>(xn, wqkv, q, k, v);

    // 3. Landmarks
    landmark_kernel<<<(BH * MM * DHD) / 256, 256>>>(q, k, ql, kl);

    // 4. Similarities (NT form)
    gemm_w<1><<<dim3(2, 32, BH), 256>>>(q, kl, sim1, nullptr, DHD, DHD, DHD, MM,
        (long)NN * DHD, (long)MM * DHD, (long)NN * MM, 0.f, 1.f, 0.f, nullptr, nullptr);
    gemm_w<1><<<dim3(2, 2, BH), 256>>>(ql, kl, a2, nullptr, DHD, DHD, DHD, MM,
        (long)MM * DHD, (long)MM * DHD, sMM, 0.f, 1.f, 0.f, nullptr, nullptr);
    gemm_w<1><<<dim3(32, 2, BH), 256>>>(ql, k, sim3, nullptr, DHD, DHD, DHD, NN,
        (long)MM * DHD, (long)NN * DHD, (long)MM * NN, 0.f, 1.f, 0.f, nullptr, nullptr);

    // 5. Softmaxes
    softmax_rows<1><<<BH * NN, 256>>>(sim1);
    softmax_rows<1><<<BH * MM, 256>>>(a2);
    softmax_rows<16><<<BH * MM, 256>>>(sim3);

    // 6. pinv init
    scal_init_kernel<<<1, 1>>>();
    colmax_kernel<<<BH * MM, 256>>>(a2);
    rowmax_kernel<<<BH * MM, 256>>>(a2);
    zinit_kernel<<<(BH * MM * MM) / 256, 256>>>(a2, z);

    // 7. Newton-Schulz iterations (w1 = 7I - xz fused into first GEMM)
    dim3 gmm(2, 2, BH);
    for (int it = 0; it < ITERS; it++) {
        float* zin  = (it & 1) ? z2 : z;
        float* zout = (it & 1) ? z  : z2;
        gemm_w<0><<<gmm, 256>>>(a2, zin, xz, w1, MM, MM, MM, MM, sMM, sMM, sMM,
                                0.f, 1.f, 7.f, nullptr, nullptr);
        gemm_w<0><<<gmm, 256>>>(xz, w1, w2, nullptr, MM, MM, MM, MM, sMM, sMM, sMM,
                                15.f, -1.f, 0.f, nullptr, nullptr);
        gemm_w<0><<<gmm, 256>>>(xz, w2, w3, nullptr, MM, MM, MM, MM, sMM, sMM, sMM,
                                13.f, -1.f, 0.f, nullptr, nullptr);
        gemm_w<0><<<gmm, 256>>>(zin, w3, zout, nullptr, MM, MM, MM, MM, sMM, sMM, sMM,
                                0.f, 0.25f, 0.f, nullptr, nullptr);
    }
    // result in z (even ITERS)

    // 8. out = a1 @ (z @ (a3 @ v))   [reassociated: saves the 17 GF a1@z GEMM]
    // av = a3 @ v via split-K (8 chunks of 512)
    gemm_n<<<dim3(1, 2, BH * 8), 256>>>(sim3, v, avp, 512, NN, DHD,
        (long)MM * NN, (long)NN * DHD, (long)MM * DHD, 8, 512L, 512L * DHD, 1.f);
    avreduce_kernel<<<(BH * MM * DHD) / 256, 256>>>(avp, av);
    // zav = z @ av
    gemm_n<<<dim3(1, 2, BH), 256>>>(z, av, zav, MM, MM, DHD,
        sMM, (long)MM * DHD, (long)MM * DHD, 1, 0L, 0L, 1.f);
    // outh = a1 @ zav
    gemm_n<<<dim3(1, 32, BH), 256>>>(sim1, zav, outh, MM, MM, DHD,
        (long)NN * MM, (long)MM * DHD, (long)NN * DHD, 1, 0L, 0L, 1.f);

    // 9. residual depthwise conv
    conv_kernel<<<(BH * NN * DHD) / 256, 256>>>(v, resw, outh);

    // 10. repack
    repack_kernel<<<(BB * NN * INNER) / 256, 256>>>(outh, rep);

    // 11. out projection + bias + residual
    gemm_w<0><<<dim3(4, 128, 1), 256>>>(rep, wout, out, nullptr, INNER, INNER, DIM, DIM,
        0L, 0L, 0L, 0.f, 1.f, 0.f, bout, x);

    (void)in_sizes; (void)n_in; (void)out_size;
}

// round 5
// speedup vs baseline: 1.4633x; 1.0928x over previous
#include <cuda_runtime.h>

// ---------------- problem constants ----------------
#define BB    4
#define NN    4096
#define DIM   512
#define HH    8
#define DHD   64
#define MM    256
#define INNER 512
#define BH    (BB*HH)
#define KK    33
#define ITERS 6

// ---------------- scratch ----------------
__device__ float g_xn  [BB*NN*DIM];
__device__ float g_q   [BH*NN*DHD];
__device__ float g_k   [BH*NN*DHD];
__device__ float g_v   [BH*NN*DHD];
__device__ float g_ql  [BH*MM*DHD];
__device__ float g_kl  [BH*MM*DHD];
__device__ float g_sim1[BH*NN*MM];
__device__ float g_sim3[BH*MM*NN];
__device__ float g_a2  [BH*MM*MM];
__device__ float g_z   [BH*MM*MM];
__device__ float g_z2  [BH*MM*MM];
__device__ float g_xz  [BH*MM*MM];
__device__ float g_w1  [BH*MM*MM];
__device__ float g_w2  [BH*MM*MM];
__device__ float g_w3  [BH*MM*MM];
__device__ float g_avp [BH*8*MM*DHD];
__device__ float g_av  [BH*MM*DHD];
__device__ float g_zav [BH*MM*DHD];
__device__ float g_outh[BH*NN*DHD];
__device__ float g_rep [BB*NN*INNER];
__device__ int   g_scalbits[2];

// ---------------- reductions ----------------
__device__ __forceinline__ float blockReduceSum256(float v, float* sh) {
    int lane = threadIdx.x & 31, wid = threadIdx.x >> 5;
    #pragma unroll
    for (int o = 16; o > 0; o >>= 1) v += __shfl_xor_sync(0xffffffffu, v, o);
    __syncthreads();
    if (lane == 0) sh[wid] = v;
    __syncthreads();
    float r = 0.f;
    #pragma unroll
    for (int i = 0; i < 8; i++) r += sh[i];
    return r;
}
__device__ __forceinline__ float blockReduceMax256(float v, float* sh) {
    int lane = threadIdx.x & 31, wid = threadIdx.x >> 5;
    #pragma unroll
    for (int o = 16; o > 0; o >>= 1) v = fmaxf(v, __shfl_xor_sync(0xffffffffu, v, o));
    __syncthreads();
    if (lane == 0) sh[wid] = v;
    __syncthreads();
    float r = -3.4e38f;
    #pragma unroll
    for (int i = 0; i < 8; i++) r = fmaxf(r, sh[i]);
    return r;
}

// ---------------- LayerNorm ----------------
__global__ void ln_kernel(const float* __restrict__ x, const float* __restrict__ w,
                          const float* __restrict__ b, float* __restrict__ o) {
    __shared__ float sh[8];
    long row = blockIdx.x;
    const float* xr = x + row * DIM;
    float v0 = xr[threadIdx.x], v1 = xr[threadIdx.x + 256];
    float s = blockReduceSum256(v0 + v1, sh);
    float mean = s * (1.f / DIM);
    float d0 = v0 - mean, d1 = v1 - mean;
    float s2 = blockReduceSum256(d0 * d0 + d1 * d1, sh);
    float rstd = rsqrtf(s2 * (1.f / DIM) + 1e-5f);
    o[row * DIM + threadIdx.x]       = d0 * rstd * w[threadIdx.x]       + b[threadIdx.x];
    o[row * DIM + threadIdx.x + 256] = d1 * rstd * w[threadIdx.x + 256] + b[threadIdx.x + 256];
}

// ========== pipelined 128x128 GEMM, 8x8/thread, double-buffered smem ==========
// C = diag*I + scale*(A@op(B)) [+bias[col]] [+add];  C2 = diag2*I - (A@op(B))
#define MAIN_COMPUTE(BUF)                                                      \
    _Pragma("unroll")                                                          \
    for (int kk = 0; kk < 16; kk++) {                                          \
        float4 x0 = *(const float4*)&As[BUF][kk][ra];                          \
        float4 x1 = *(const float4*)&As[BUF][kk][rb];                          \
        float4 y0 = *(const float4*)&Bs[BUF][kk][ca];                          \
        float4 y1 = *(const float4*)&Bs[BUF][kk][cb];                          \
        float av_[8] = {x0.x,x0.y,x0.z,x0.w,x1.x,x1.y,x1.z,x1.w};              \
        float bv_[8] = {y0.x,y0.y,y0.z,y0.w,y1.x,y1.y,y1.z,y1.w};              \
        _Pragma("unroll")                                                      \
        for (int i = 0; i < 8; i++)                                            \
            _Pragma("unroll")                                                  \
            for (int j = 0; j < 8; j++) acc[i][j] += av_[i] * bv_[j];          \
    }

#define STORE_A(BUF)                                                           \
    As[BUF][ak+0][ar]=pa0.x; As[BUF][ak+1][ar]=pa0.y;                          \
    As[BUF][ak+2][ar]=pa0.z; As[BUF][ak+3][ar]=pa0.w;                          \
    As[BUF][ak+4][ar]=pa1.x; As[BUF][ak+5][ar]=pa1.y;                          \
    As[BUF][ak+6][ar]=pa1.z; As[BUF][ak+7][ar]=pa1.w;

template<int NT>
__global__ __launch_bounds__(256) void gemm_w(
    const float* __restrict__ A, const float* __restrict__ B,
    float* __restrict__ C, float* __restrict__ C2,
    int K, int lda, int ldb, int ldc, long sA, long sB, long sC,
    float diag, float scale, float diag2,
    const float* __restrict__ bias, const float* __restrict__ add)
{
    int z = blockIdx.z;
    A += (long)z * sA;  B += (long)z * sB;  C += (long)z * sC;
    if (C2) C2 += (long)z * sC;
    int row0 = blockIdx.y * 128, col0 = blockIdx.x * 128;
    __shared__ float As[2][16][128];
    __shared__ float Bs[2][16][128];
    int tid = threadIdx.x, lane = tid & 31, warp = tid >> 5;
    int wr = (warp >> 1) * 32, wc = (warp & 1) * 64;
    int ra = wr + (lane >> 3) * 4, rb = ra + 16;
    int ca = wc + (lane & 7) * 4,  cb = ca + 32;
    int ar = tid >> 1, ak = (tid & 1) * 8;
    int bk = tid >> 4, bc = (tid & 15) * 8;
    const float* Arow = A + (long)(row0 + ar) * lda;
    float acc[8][8] = {};
    float4 pa0, pa1, pb0, pb1;
    // prologue: k-tile 0 -> regs -> buf 0
    pa0 = *(const float4*)(Arow + ak);
    pa1 = *(const float4*)(Arow + ak + 4);
    if (NT) {
        const float* Brow = B + (long)(col0 + ar) * ldb;
        pb0 = *(const float4*)(Brow + ak);
        pb1 = *(const float4*)(Brow + ak + 4);
    } else {
        pb0 = *(const float4*)(B + (long)bk * ldb + col0 + bc);
        pb1 = *(const float4*)(B + (long)bk * ldb + col0 + bc + 4);
    }
    STORE_A(0)
    if (NT) {
        Bs[0][ak+0][ar]=pb0.x; Bs[0][ak+1][ar]=pb0.y; Bs[0][ak+2][ar]=pb0.z; Bs[0][ak+3][ar]=pb0.w;
        Bs[0][ak+4][ar]=pb1.x; Bs[0][ak+5][ar]=pb1.y; Bs[0][ak+6][ar]=pb1.z; Bs[0][ak+7][ar]=pb1.w;
    } else {
        *(float4*)&Bs[0][bk][bc]     = pb0;
        *(float4*)&Bs[0][bk][bc + 4] = pb1;
    }
    __syncthreads();
    int KT = K >> 4;
    for (int kt = 0; kt < KT; kt++) {
        int cur = kt & 1, nxt = cur ^ 1;
        if (kt + 1 < KT) {
            int k0 = (kt + 1) << 4;
            pa0 = *(const float4*)(Arow + k0 + ak);
            pa1 = *(const float4*)(Arow + k0 + ak + 4);
            if (NT) {
                const float* Brow = B + (long)(col0 + ar) * ldb;
                pb0 = *(const float4*)(Brow + k0 + ak);
                pb1 = *(const float4*)(Brow + k0 + ak + 4);
            } else {
                pb0 = *(const float4*)(B + (long)(k0 + bk) * ldb + col0 + bc);
                pb1 = *(const float4*)(B + (long)(k0 + bk) * ldb + col0 + bc + 4);
            }
        }
        if (cur == 0) { MAIN_COMPUTE(0) } else { MAIN_COMPUTE(1) }
        if (kt + 1 < KT) {
            if (nxt == 0) { STORE_A(0) } else { STORE_A(1) }
            if (NT) {
                Bs[nxt][ak+0][ar]=pb0.x; Bs[nxt][ak+1][ar]=pb0.y; Bs[nxt][ak+2][ar]=pb0.z; Bs[nxt][ak+3][ar]=pb0.w;
                Bs[nxt][ak+4][ar]=pb1.x; Bs[nxt][ak+5][ar]=pb1.y; Bs[nxt][ak+6][ar]=pb1.z; Bs[nxt][ak+7][ar]=pb1.w;
            } else {
                *(float4*)&Bs[nxt][bk][bc]     = pb0;
                *(float4*)&Bs[nxt][bk][bc + 4] = pb1;
            }
            __syncthreads();
        }
    }
    #pragma unroll
    for (int i = 0; i < 8; i++) {
        int lrow = (i < 4) ? (ra + i) : (rb + i - 4);
        int grow = row0 + lrow;
        #pragma unroll
        for (int half = 0; half < 2; half++) {
            int gc0 = col0 + (half ? cb : ca);
            float4 v; float* vp = &v.x;
            #pragma unroll
            for (int j = 0; j < 4; j++) {
                float val = scale * acc[i][half * 4 + j];
                int gcol = gc0 + j;
                if (grow == gcol) val += diag;
                if (bias) val += bias[gcol];
                if (add)  val += add[(long)grow * ldc + gcol];
                vp[j] = val;
            }
            *(float4*)(C + (long)grow * ldc + gc0) = v;
            if (C2) {
                float4 w; float* wp = &w.x;
                #pragma unroll
                for (int j = 0; j < 4; j++) {
                    float val = -acc[i][half * 4 + j];
                    if (grow == gc0 + j) val += diag2;
                    wp[j] = val;
                }
                *(float4*)(C2 + (long)grow * ldc + gc0) = w;
            }
        }
    }
}

// ---- QKV: pipelined core, scatter epilogue into [B,H,N,D] with q scaling ----
__global__ __launch_bounds__(256) void gemm_qkv(
    const float* __restrict__ A, const float* __restrict__ B,
    float* __restrict__ Q, float* __restrict__ Kp, float* __restrict__ V)
{
    const int lda = DIM, ldb = 3 * INNER;
    int row0 = blockIdx.y * 128, col0 = blockIdx.x * 128;
    __shared__ float As[2][16][128];
    __shared__ float Bs[2][16][128];
    int tid = threadIdx.x, lane = tid & 31, warp = tid >> 5;
    int wr = (warp >> 1) * 32, wc = (warp & 1) * 64;
    int ra = wr + (lane >> 3) * 4, rb = ra + 16;
    int ca = wc + (lane & 7) * 4,  cb = ca + 32;
    int ar = tid >> 1, ak = (tid & 1) * 8;
    int bk = tid >> 4, bc = (tid & 15) * 8;
    const float* Arow = A + (long)(row0 + ar) * lda;
    float acc[8][8] = {};
    float4 pa0, pa1, pb0, pb1;
    pa0 = *(const float4*)(Arow + ak);
    pa1 = *(const float4*)(Arow + ak + 4);
    pb0 = *(const float4*)(B + (long)bk * ldb + col0 + bc);
    pb1 = *(const float4*)(B + (long)bk * ldb + col0 + bc + 4);
    STORE_A(0)
    *(float4*)&Bs[0][bk][bc]     = pb0;
    *(float4*)&Bs[0][bk][bc + 4] = pb1;
    __syncthreads();
    const int KT = DIM >> 4;
    for (int kt = 0; kt < KT; kt++) {
        int cur = kt & 1, nxt = cur ^ 1;
        if (kt + 1 < KT) {
            int k0 = (kt + 1) << 4;
            pa0 = *(const float4*)(Arow + k0 + ak);
            pa1 = *(const float4*)(Arow + k0 + ak + 4);
            pb0 = *(const float4*)(B + (long)(k0 + bk) * ldb + col0 + bc);
            pb1 = *(const float4*)(B + (long)(k0 + bk) * ldb + col0 + bc + 4);
        }
        if (cur == 0) { MAIN_COMPUTE(0) } else { MAIN_COMPUTE(1) }
        if (kt + 1 < KT) {
            if (nxt == 0) { STORE_A(0) } else { STORE_A(1) }
            *(float4*)&Bs[nxt][bk][bc]     = pb0;
            *(float4*)&Bs[nxt][bk][bc + 4] = pb1;
            __syncthreads();
        }
    }
    #pragma unroll
    for (int i = 0; i < 8; i++) {
        int grow = row0 + ((i < 4) ? (ra + i) : (rb + i - 4));
        int bb = grow >> 12, nn = grow & (NN - 1);
        #pragma unroll
        for (int j = 0; j < 8; j++) {
            int gcol = col0 + ((j < 4) ? (ca + j) : (cb + j - 4));
            int part = gcol / INNER, inner = gcol % INNER;
            int h = inner >> 6, d = inner & 63;
            long dst = ((long)((bb * HH + h) * NN + nn) << 6) + d;
            float val = acc[i][j];
            if (part == 0)      Q[dst]  = val * 0.125f;
            else if (part == 1) Kp[dst] = val;
            else                V[dst]  = val;
        }
    }
}

// ===== narrow GEMM (N=64), pipelined, split-K batching =====
__global__ __launch_bounds__(256) void gemm_n(
    const float* __restrict__ A, const float* __restrict__ B, float* __restrict__ C,
    int K, int lda, int ldb, long sA, long sB, long sC,
    int CPB, long chA, long chB, float scale)
{
    int z = blockIdx.z;
    int bh = z / CPB, ch = z - bh * CPB;
    A += (long)bh * sA + (long)ch * chA;
    B += (long)bh * sB + (long)ch * chB;
    C += (long)z * sC;
    int row0 = blockIdx.y * 128;
    __shared__ float As[2][16][128];
    __shared__ float Bs[2][16][64];
    int tid = threadIdx.x, lane = tid & 31, warp = tid >> 5;
    int ra = warp * 16 + (lane >> 3) * 4;
    int c4 = (lane & 7) * 4;
    int ar = tid >> 1, ak = (tid & 1) * 8;
    int bk = tid >> 4, bc = (tid & 15) * 4;
    const float* Arow = A + (long)(row0 + ar) * lda;
    float acc[4][8] = {};
    float4 pa0, pa1, pb0;
    pa0 = *(const float4*)(Arow + ak);
    pa1 = *(const float4*)(Arow + ak + 4);
    pb0 = *(const float4*)(B + (long)bk * ldb + bc);
    STORE_A(0)
    *(float4*)&Bs[0][bk][bc] = pb0;
    __syncthreads();
    int KT = K >> 4;
    for (int kt = 0; kt < KT; kt++) {
        int cur = kt & 1, nxt = cur ^ 1;
        if (kt + 1 < KT) {
            int k0 = (kt + 1) << 4;
            pa0 = *(const float4*)(Arow + k0 + ak);
            pa1 = *(const float4*)(Arow + k0 + ak + 4);
            pb0 = *(const float4*)(B + (long)(k0 + bk) * ldb + bc);
        }
        #pragma unroll
        for (int kk = 0; kk < 16; kk++) {
            float4 x0 = *(const float4*)&As[cur][kk][ra];
            float4 y0 = *(const float4*)&Bs[cur][kk][c4];
            float4 y1 = *(const float4*)&Bs[cur][kk][c4 + 32];
            float av_[4] = {x0.x,x0.y,x0.z,x0.w};
            float bv_[8] = {y0.x,y0.y,y0.z,y0.w,y1.x,y1.y,y1.z,y1.w};
            #pragma unroll
            for (int i = 0; i < 4; i++)
                #pragma unroll
                for (int j = 0; j < 8; j++) acc[i][j] += av_[i] * bv_[j];
        }
        if (kt + 1 < KT) {
            if (nxt == 0) { STORE_A(0) } else { STORE_A(1) }
            *(float4*)&Bs[nxt][bk][bc] = pb0;
            __syncthreads();
        }
    }
    #pragma unroll
    for (int i = 0; i < 4; i++) {
        int grow = row0 + ra + i;
        float4 v0, v1;
        v0.x = scale*acc[i][0]; v0.y = scale*acc[i][1]; v0.z = scale*acc[i][2]; v0.w = scale*acc[i][3];
        v1.x = scale*acc[i][4]; v1.y = scale*acc[i][5]; v1.z = scale*acc[i][6]; v1.w = scale*acc[i][7];
        *(float4*)(C + (long)grow * 64 + c4)      = v0;
        *(float4*)(C + (long)grow * 64 + c4 + 32) = v1;
    }
}

// split-K reduce for av
__global__ void avreduce_kernel(const float* __restrict__ p, float* __restrict__ o) {
    long idx = (long)blockIdx.x * 256 + threadIdx.x;
    long bh = idx >> 14;
    long t = idx & 16383;
    float s = 0.f;
    #pragma unroll
    for (int c = 0; c < 8; c++) s += p[((bh * 8 + c) << 14) + t];
    o[idx] = s;
}

// ---------------- landmarks ----------------
__global__ void landmark_kernel(const float* __restrict__ q, const float* __restrict__ k,
                                float* __restrict__ ql, float* __restrict__ kl) {
    long idx = (long)blockIdx.x * 256 + threadIdx.x;
    int d = idx & 63;
    int m = (idx >> 6) & (MM - 1);
    long bh = idx >> 14;
    long base = ((bh * NN + (long)m * 16) << 6) + d;
    float sq = 0.f, sk = 0.f;
    #pragma unroll
    for (int j = 0; j < 16; j++) { sq += q[base + (long)j * 64]; sk += k[base + (long)j * 64]; }
    ql[idx] = sq * (1.f / 16.f);
    kl[idx] = sk * (1.f / 16.f);
}

// ---------------- softmax ----------------
template <int CNT>
__global__ void softmax_rows(float* __restrict__ X) {
    __shared__ float sh[8];
    long row = blockIdx.x;
    float* xr = X + row * (long)(CNT * 256);
    float loc[CNT];
    float mx = -3.4e38f;
    #pragma unroll
    for (int i = 0; i < CNT; i++) { loc[i] = xr[threadIdx.x + i * 256]; mx = fmaxf(mx, loc[i]); }
    mx = blockReduceMax256(mx, sh);
    float s = 0.f;
    #pragma unroll
    for (int i = 0; i < CNT; i++) { loc[i] = expf(loc[i] - mx); s += loc[i]; }
    s = blockReduceSum256(s, sh);
    float inv = 1.f / s;
    #pragma unroll
    for (int i = 0; i < CNT; i++) xr[threadIdx.x + i * 256] = loc[i] * inv;
}

// ---------------- pinv init ----------------
__global__ void scal_init_kernel() { g_scalbits[0] = 0; g_scalbits[1] = 0; }

__global__ void colmax_kernel(const float* __restrict__ a2) {
    __shared__ float sh[8];
    long row = blockIdx.x;
    float v = fabsf(a2[row * MM + threadIdx.x]);
    v = blockReduceSum256(v, sh);
    if (threadIdx.x == 0) atomicMax(&g_scalbits[0], __float_as_int(v));
}
__global__ void rowmax_kernel(const float* __restrict__ a2) {
    __shared__ float sh[8];
    long col = blockIdx.x;
    long bh = col >> 8; int j = col & (MM - 1);
    float v = fabsf(a2[(bh << 16) + (long)threadIdx.x * MM + j]);
    v = blockReduceSum256(v, sh);
    if (threadIdx.x == 0) atomicMax(&g_scalbits[1], __float_as_int(v));
}
__global__ void zinit_kernel(const float* __restrict__ a2, float* __restrict__ z) {
    long idx = (long)blockIdx.x * 256 + threadIdx.x;
    float denom = __int_as_float(g_scalbits[0]) * __int_as_float(g_scalbits[1]);
    long bh = idx >> 16; int i = (idx >> 8) & 255, j = idx & 255;
    z[idx] = a2[(bh << 16) + (long)j * MM + i] / denom;
}

// ---------------- depthwise conv: outh += conv(v) ----------------
__global__ void conv_kernel(const float* __restrict__ v, const float* __restrict__ w,
                            float* __restrict__ outh) {
    long idx = (long)blockIdx.x * 256 + threadIdx.x;
    int d = idx & 63;
    int n = (idx >> 6) & (NN - 1);
    long bh = idx >> 18;
    int h = (int)(bh & 7);
    const float* vb = v + ((bh * NN) << 6) + d;
    float s = 0.f;
    #pragma unroll
    for (int kk = 0; kk < KK; kk++) {
        int nn = n + kk - KK / 2;
        if (nn >= 0 && nn < NN) s += w[h * KK + kk] * vb[(long)nn * 64];
    }
    outh[idx] += s;
}

// ---------------- repack [B,H,N,D] -> [B,N,H*D] ----------------
__global__ void repack_kernel(const float* __restrict__ outh, float* __restrict__ rep) {
    long idx = (long)blockIdx.x * 256 + threadIdx.x;
    int c = idx & (INNER - 1);
    long r = idx >> 9;
    int h = c >> 6, d = c & 63;
    long bb = r >> 12, nn = r & (NN - 1);
    rep[idx] = outh[(((bb * HH + h) * NN + nn) << 6) + d];
}

// ---------------- host ----------------
static inline void* sym(const void* s) { void* p = nullptr; cudaGetSymbolAddress(&p, s); return p; }

extern "C" void kernel_launch(void* const* d_in, const int* in_sizes, int n_in,
                              void* d_out, int out_size) {
    const float* x    = (const float*)d_in[0];
    const float* nw   = (const float*)d_in[1];
    const float* nb   = (const float*)d_in[2];
    const float* wqkv = (const float*)d_in[3];
    const float* wout = (const float*)d_in[4];
    const float* bout = (const float*)d_in[5];
    const float* resw = (const float*)d_in[6];
    float* out = (float*)d_out;

    float* xn   = (float*)sym(g_xn);
    float* q    = (float*)sym(g_q);
    float* k    = (float*)sym(g_k);
    float* v    = (float*)sym(g_v);
    float* ql   = (float*)sym(g_ql);
    float* kl   = (float*)sym(g_kl);
    float* sim1 = (float*)sym(g_sim1);
    float* sim3 = (float*)sym(g_sim3);
    float* a2   = (float*)sym(g_a2);
    float* z    = (float*)sym(g_z);
    float* z2   = (float*)sym(g_z2);
    float* xz   = (float*)sym(g_xz);
    float* w1   = (float*)sym(g_w1);
    float* w2   = (float*)sym(g_w2);
    float* w3   = (float*)sym(g_w3);
    float* avp  = (float*)sym(g_avp);
    float* av   = (float*)sym(g_av);
    float* zav  = (float*)sym(g_zav);
    float* outh = (float*)sym(g_outh);
    float* rep  = (float*)sym(g_rep);

    const long sMM = (long)MM * MM;

    // 1. LayerNorm
    ln_kernel<<<BB * NN, 256>>>(x, nw, nb, xn);

    // 2. QKV projection
    gemm_qkv<<<dim3(12, 128, 1), 256>>>(xn, wqkv, q, k, v);

    // 3. Landmarks
    landmark_kernel<<<(BH * MM * DHD) / 256, 256>>>(q, k, ql, kl);

    // 4. Similarities (NT form)
    gemm_w<1><<<dim3(2, 32, BH), 256>>>(q, kl, sim1, nullptr, DHD, DHD, DHD, MM,
        (long)NN * DHD, (long)MM * DHD, (long)NN * MM, 0.f, 1.f, 0.f, nullptr, nullptr);
    gemm_w<1><<<dim3(2, 2, BH), 256>>>(ql, kl, a2, nullptr, DHD, DHD, DHD, MM,
        (long)MM * DHD, (long)MM * DHD, sMM, 0.f, 1.f, 0.f, nullptr, nullptr);
    gemm_w<1><<<dim3(32, 2, BH), 256>>>(ql, k, sim3, nullptr, DHD, DHD, DHD, NN,
        (long)MM * DHD, (long)NN * DHD, (long)MM * NN, 0.f, 1.f, 0.f, nullptr, nullptr);

    // 5. Softmaxes
    softmax_rows<1><<<BH * NN, 256>>>(sim1);
    softmax_rows<1><<<BH * MM, 256>>>(a2);
    softmax_rows<16><<<BH * MM, 256>>>(sim3);

    // 6. pinv init
    scal_init_kernel<<<1, 1>>>();
    colmax_kernel<<<BH * MM, 256>>>(a2);
    rowmax_kernel<<<BH * MM, 256>>>(a2);
    zinit_kernel<<<(BH * MM * MM) / 256, 256>>>(a2, z);

    // 7. Newton-Schulz (w1 = 7I - xz fused into first GEMM)
    dim3 gmm(2, 2, BH);
    for (int it = 0; it < ITERS; it++) {
        float* zin  = (it & 1) ? z2 : z;
        float* zout = (it & 1) ? z  : z2;
        gemm_w<0><<<gmm, 256>>>(a2, zin, xz, w1, MM, MM, MM, MM, sMM, sMM, sMM,
                                0.f, 1.f, 7.f, nullptr, nullptr);
        gemm_w<0><<<gmm, 256>>>(xz, w1, w2, nullptr, MM, MM, MM, MM, sMM, sMM, sMM,
                                15.f, -1.f, 0.f, nullptr, nullptr);
        gemm_w<0><<<gmm, 256>>>(xz, w2, w3, nullptr, MM, MM, MM, MM, sMM, sMM, sMM,
                                13.f, -1.f, 0.f, nullptr, nullptr);
        gemm_w<0><<<gmm, 256>>>(zin, w3, zout, nullptr, MM, MM, MM, MM, sMM, sMM, sMM,
                                0.f, 0.25f, 0.f, nullptr, nullptr);
    }
    // result in z (even ITERS)

    // 8. out = a1 @ (z @ (a3 @ v))
    gemm_n<<<dim3(1, 2, BH * 8), 256>>>(sim3, v, avp, 512, NN, DHD,
        (long)MM * NN, (long)NN * DHD, (long)MM * DHD, 8, 512L, 512L * DHD, 1.f);
    avreduce_kernel<<<(BH * MM * DHD) / 256, 256>>>(avp, av);
    gemm_n<<<dim3(1, 2, BH), 256>>>(z, av, zav, MM, MM, DHD,
        sMM, (long)MM * DHD, (long)MM * DHD, 1, 0L, 0L, 1.f);
    gemm_n<<<dim3(1, 32, BH), 256>>>(sim1, zav, outh, MM, MM, DHD,
        (long)NN * MM, (long)MM * DHD, (long)NN * DHD, 1, 0L, 0L, 1.f);

    // 9. residual depthwise conv
    conv_kernel<<<(BH * NN * DHD) / 256, 256>>>(v, resw, outh);

    // 10. repack
    repack_kernel<<<(BB * NN * INNER) / 256, 256>>>(outh, rep);

    // 11. out projection + bias + residual
    gemm_w<0><<<dim3(4, 128, 1), 256>>>(rep, wout, out, nullptr, INNER, INNER, DIM, DIM,
        0L, 0L, 0L, 0.f, 1.f, 0.f, bout, x);

    (void)in_sizes; (void)n_in; (void)out_size;
}

// round 6
// speedup vs baseline: 1.4648x; 1.0010x over previous
#include <cuda_runtime.h>

// ---------------- problem constants ----------------
#define BB    4
#define NN    4096
#define DIM   512
#define HH    8
#define DHD   64
#define MM    256
#define INNER 512
#define BH    (BB*HH)
#define KK    33
#define ITERS 6

// ---------------- scratch ----------------
__device__ float g_xn  [BB*NN*DIM];
__device__ float g_q   [BH*NN*DHD];
__device__ float g_k   [BH*NN*DHD];
__device__ float g_v   [BH*NN*DHD];
__device__ float g_ql  [BH*MM*DHD];
__device__ float g_kl  [BH*MM*DHD];
__device__ float g_sim1[BH*NN*MM];
__device__ float g_sim3[BH*MM*NN];
__device__ float g_a2  [BH*MM*MM];
__device__ float g_z   [BH*MM*MM];
__device__ float g_z2  [BH*MM*MM];
__device__ float g_xz  [BH*MM*MM];
__device__ float g_w1  [BH*MM*MM];
__device__ float g_w2  [BH*MM*MM];
__device__ float g_w3  [BH*MM*MM];
__device__ float g_avp [BH*8*MM*DHD];
__device__ float g_av  [BH*MM*DHD];
__device__ float g_zav [BH*MM*DHD];
__device__ float g_outh[BH*NN*DHD];
__device__ float g_rep [BB*NN*INNER];
__device__ int   g_scalbits[2];

// ---------------- reductions ----------------
__device__ __forceinline__ float blockReduceSum256(float v, float* sh) {
    int lane = threadIdx.x & 31, wid = threadIdx.x >> 5;
    #pragma unroll
    for (int o = 16; o > 0; o >>= 1) v += __shfl_xor_sync(0xffffffffu, v, o);
    __syncthreads();
    if (lane == 0) sh[wid] = v;
    __syncthreads();
    float r = 0.f;
    #pragma unroll
    for (int i = 0; i < 8; i++) r += sh[i];
    return r;
}
__device__ __forceinline__ float blockReduceMax256(float v, float* sh) {
    int lane = threadIdx.x & 31, wid = threadIdx.x >> 5;
    #pragma unroll
    for (int o = 16; o > 0; o >>= 1) v = fmaxf(v, __shfl_xor_sync(0xffffffffu, v, o));
    __syncthreads();
    if (lane == 0) sh[wid] = v;
    __syncthreads();
    float r = -3.4e38f;
    #pragma unroll
    for (int i = 0; i < 8; i++) r = fmaxf(r, sh[i]);
    return r;
}

// ---------------- LayerNorm ----------------
__global__ void ln_kernel(const float* __restrict__ x, const float* __restrict__ w,
                          const float* __restrict__ b, float* __restrict__ o) {
    __shared__ float sh[8];
    long row = blockIdx.x;
    const float* xr = x + row * DIM;
    float v0 = xr[threadIdx.x], v1 = xr[threadIdx.x + 256];
    float s = blockReduceSum256(v0 + v1, sh);
    float mean = s * (1.f / DIM);
    float d0 = v0 - mean, d1 = v1 - mean;
    float s2 = blockReduceSum256(d0 * d0 + d1 * d1, sh);
    float rstd = rsqrtf(s2 * (1.f / DIM) + 1e-5f);
    o[row * DIM + threadIdx.x]       = d0 * rstd * w[threadIdx.x]       + b[threadIdx.x];
    o[row * DIM + threadIdx.x + 256] = d1 * rstd * w[threadIdx.x + 256] + b[threadIdx.x + 256];
}

// ========== pipelined 128x128 GEMM, 8x8/thread, double-buffered smem ==========
// C = diag*I + scale*(A@op(B)) [+bias[col]] [+add];  C2 = diag2*I - (A@op(B))
#define MAIN_COMPUTE(BUF)                                                      \
    _Pragma("unroll")                                                          \
    for (int kk = 0; kk < 16; kk++) {                                          \
        float4 x0 = *(const float4*)&As[BUF][kk][ra];                          \
        float4 x1 = *(const float4*)&As[BUF][kk][rb];                          \
        float4 y0 = *(const float4*)&Bs[BUF][kk][ca];                          \
        float4 y1 = *(const float4*)&Bs[BUF][kk][cb];                          \
        float av_[8] = {x0.x,x0.y,x0.z,x0.w,x1.x,x1.y,x1.z,x1.w};              \
        float bv_[8] = {y0.x,y0.y,y0.z,y0.w,y1.x,y1.y,y1.z,y1.w};              \
        _Pragma("unroll")                                                      \
        for (int i = 0; i < 8; i++)                                            \
            _Pragma("unroll")                                                  \
            for (int j = 0; j < 8; j++) acc[i][j] += av_[i] * bv_[j];          \
    }

#define STORE_A(BUF)                                                           \
    As[BUF][ak+0][ar]=pa0.x; As[BUF][ak+1][ar]=pa0.y;                          \
    As[BUF][ak+2][ar]=pa0.z; As[BUF][ak+3][ar]=pa0.w;                          \
    As[BUF][ak+4][ar]=pa1.x; As[BUF][ak+5][ar]=pa1.y;                          \
    As[BUF][ak+6][ar]=pa1.z; As[BUF][ak+7][ar]=pa1.w;

template<int NT>
__global__ __launch_bounds__(256) void gemm_w(
    const float* __restrict__ A, const float* __restrict__ B,
    float* __restrict__ C, float* __restrict__ C2,
    int K, int lda, int ldb, int ldc, long sA, long sB, long sC,
    float diag, float scale, float diag2,
    const float* __restrict__ bias, const float* __restrict__ add)
{
    int z = blockIdx.z;
    A += (long)z * sA;  B += (long)z * sB;  C += (long)z * sC;
    if (C2) C2 += (long)z * sC;
    int row0 = blockIdx.y * 128, col0 = blockIdx.x * 128;
    __shared__ float As[2][16][128];
    __shared__ float Bs[2][16][128];
    int tid = threadIdx.x, lane = tid & 31, warp = tid >> 5;
    int wr = (warp >> 1) * 32, wc = (warp & 1) * 64;
    int ra = wr + (lane >> 3) * 4, rb = ra + 16;
    int ca = wc + (lane & 7) * 4,  cb = ca + 32;
    int ar = tid >> 1, ak = (tid & 1) * 8;
    int bk = tid >> 4, bc = (tid & 15) * 8;
    const float* Arow = A + (long)(row0 + ar) * lda;
    float acc[8][8] = {};
    float4 pa0, pa1, pb0, pb1;
    // prologue: k-tile 0 -> regs -> buf 0
    pa0 = *(const float4*)(Arow + ak);
    pa1 = *(const float4*)(Arow + ak + 4);
    if (NT) {
        const float* Brow = B + (long)(col0 + ar) * ldb;
        pb0 = *(const float4*)(Brow + ak);
        pb1 = *(const float4*)(Brow + ak + 4);
    } else {
        pb0 = *(const float4*)(B + (long)bk * ldb + col0 + bc);
        pb1 = *(const float4*)(B + (long)bk * ldb + col0 + bc + 4);
    }
    STORE_A(0)
    if (NT) {
        Bs[0][ak+0][ar]=pb0.x; Bs[0][ak+1][ar]=pb0.y; Bs[0][ak+2][ar]=pb0.z; Bs[0][ak+3][ar]=pb0.w;
        Bs[0][ak+4][ar]=pb1.x; Bs[0][ak+5][ar]=pb1.y; Bs[0][ak+6][ar]=pb1.z; Bs[0][ak+7][ar]=pb1.w;
    } else {
        *(float4*)&Bs[0][bk][bc]     = pb0;
        *(float4*)&Bs[0][bk][bc + 4] = pb1;
    }
    __syncthreads();
    int KT = K >> 4;
    for (int kt = 0; kt < KT; kt++) {
        int cur = kt & 1, nxt = cur ^ 1;
        if (kt + 1 < KT) {
            int k0 = (kt + 1) << 4;
            pa0 = *(const float4*)(Arow + k0 + ak);
            pa1 = *(const float4*)(Arow + k0 + ak + 4);
            if (NT) {
                const float* Brow = B + (long)(col0 + ar) * ldb;
                pb0 = *(const float4*)(Brow + k0 + ak);
                pb1 = *(const float4*)(Brow + k0 + ak + 4);
            } else {
                pb0 = *(const float4*)(B + (long)(k0 + bk) * ldb + col0 + bc);
                pb1 = *(const float4*)(B + (long)(k0 + bk) * ldb + col0 + bc + 4);
            }
        }
        if (cur == 0) { MAIN_COMPUTE(0) } else { MAIN_COMPUTE(1) }
        if (kt + 1 < KT) {
            if (nxt == 0) { STORE_A(0) } else { STORE_A(1) }
            if (NT) {
                Bs[nxt][ak+0][ar]=pb0.x; Bs[nxt][ak+1][ar]=pb0.y; Bs[nxt][ak+2][ar]=pb0.z; Bs[nxt][ak+3][ar]=pb0.w;
                Bs[nxt][ak+4][ar]=pb1.x; Bs[nxt][ak+5][ar]=pb1.y; Bs[nxt][ak+6][ar]=pb1.z; Bs[nxt][ak+7][ar]=pb1.w;
            } else {
                *(float4*)&Bs[nxt][bk][bc]     = pb0;
                *(float4*)&Bs[nxt][bk][bc + 4] = pb1;
            }
            __syncthreads();
        }
    }
    #pragma unroll
    for (int i = 0; i < 8; i++) {
        int lrow = (i < 4) ? (ra + i) : (rb + i - 4);
        int grow = row0 + lrow;
        #pragma unroll
        for (int half = 0; half < 2; half++) {
            int gc0 = col0 + (half ? cb : ca);
            float4 v; float* vp = &v.x;
            #pragma unroll
            for (int j = 0; j < 4; j++) {
                float val = scale * acc[i][half * 4 + j];
                int gcol = gc0 + j;
                if (grow == gcol) val += diag;
                if (bias) val += bias[gcol];
                if (add)  val += add[(long)grow * ldc + gcol];
                vp[j] = val;
            }
            *(float4*)(C + (long)grow * ldc + gc0) = v;
            if (C2) {
                float4 w; float* wp = &w.x;
                #pragma unroll
                for (int j = 0; j < 4; j++) {
                    float val = -acc[i][half * 4 + j];
                    if (grow == gc0 + j) val += diag2;
                    wp[j] = val;
                }
                *(float4*)(C2 + (long)grow * ldc + gc0) = w;
            }
        }
    }
}

// ---- QKV: pipelined core, scatter epilogue into [B,H,N,D] with q scaling ----
__global__ __launch_bounds__(256) void gemm_qkv(
    const float* __restrict__ A, const float* __restrict__ B,
    float* __restrict__ Q, float* __restrict__ Kp, float* __restrict__ V)
{
    const int lda = DIM, ldb = 3 * INNER;
    int row0 = blockIdx.y * 128, col0 = blockIdx.x * 128;
    __shared__ float As[2][16][128];
    __shared__ float Bs[2][16][128];
    int tid = threadIdx.x, lane = tid & 31, warp = tid >> 5;
    int wr = (warp >> 1) * 32, wc = (warp & 1) * 64;
    int ra = wr + (lane >> 3) * 4, rb = ra + 16;
    int ca = wc + (lane & 7) * 4,  cb = ca + 32;
    int ar = tid >> 1, ak = (tid & 1) * 8;
    int bk = tid >> 4, bc = (tid & 15) * 8;
    const float* Arow = A + (long)(row0 + ar) * lda;
    float acc[8][8] = {};
    float4 pa0, pa1, pb0, pb1;
    pa0 = *(const float4*)(Arow + ak);
    pa1 = *(const float4*)(Arow + ak + 4);
    pb0 = *(const float4*)(B + (long)bk * ldb + col0 + bc);
    pb1 = *(const float4*)(B + (long)bk * ldb + col0 + bc + 4);
    STORE_A(0)
    *(float4*)&Bs[0][bk][bc]     = pb0;
    *(float4*)&Bs[0][bk][bc + 4] = pb1;
    __syncthreads();
    const int KT = DIM >> 4;
    for (int kt = 0; kt < KT; kt++) {
        int cur = kt & 1, nxt = cur ^ 1;
        if (kt + 1 < KT) {
            int k0 = (kt + 1) << 4;
            pa0 = *(const float4*)(Arow + k0 + ak);
            pa1 = *(const float4*)(Arow + k0 + ak + 4);
            pb0 = *(const float4*)(B + (long)(k0 + bk) * ldb + col0 + bc);
            pb1 = *(const float4*)(B + (long)(k0 + bk) * ldb + col0 + bc + 4);
        }
        if (cur == 0) { MAIN_COMPUTE(0) } else { MAIN_COMPUTE(1) }
        if (kt + 1 < KT) {
            if (nxt == 0) { STORE_A(0) } else { STORE_A(1) }
            *(float4*)&Bs[nxt][bk][bc]     = pb0;
            *(float4*)&Bs[nxt][bk][bc + 4] = pb1;
            __syncthreads();
        }
    }
    #pragma unroll
    for (int i = 0; i < 8; i++) {
        int grow = row0 + ((i < 4) ? (ra + i) : (rb + i - 4));
        int bb = grow >> 12, nn = grow & (NN - 1);
        #pragma unroll
        for (int j = 0; j < 8; j++) {
            int gcol = col0 + ((j < 4) ? (ca + j) : (cb + j - 4));
            int part = gcol / INNER, inner = gcol % INNER;
            int h = inner >> 6, d = inner & 63;
            long dst = ((long)((bb * HH + h) * NN + nn) << 6) + d;
            float val = acc[i][j];
            if (part == 0)      Q[dst]  = val * 0.125f;
            else if (part == 1) Kp[dst] = val;
            else                V[dst]  = val;
        }
    }
}

// ===== narrow GEMM (N=64), pipelined, split-K batching =====
__global__ __launch_bounds__(256) void gemm_n(
    const float* __restrict__ A, const float* __restrict__ B, float* __restrict__ C,
    int K, int lda, int ldb, long sA, long sB, long sC,
    int CPB, long chA, long chB, float scale)
{
    int z = blockIdx.z;
    int bh = z / CPB, ch = z - bh * CPB;
    A += (long)bh * sA + (long)ch * chA;
    B += (long)bh * sB + (long)ch * chB;
    C += (long)z * sC;
    int row0 = blockIdx.y * 128;
    __shared__ float As[2][16][128];
    __shared__ float Bs[2][16][64];
    int tid = threadIdx.x, lane = tid & 31, warp = tid >> 5;
    int ra = warp * 16 + (lane >> 3) * 4;
    int c4 = (lane & 7) * 4;
    int ar = tid >> 1, ak = (tid & 1) * 8;
    int bk = tid >> 4, bc = (tid & 15) * 4;
    const float* Arow = A + (long)(row0 + ar) * lda;
    float acc[4][8] = {};
    float4 pa0, pa1, pb0;
    pa0 = *(const float4*)(Arow + ak);
    pa1 = *(const float4*)(Arow + ak + 4);
    pb0 = *(const float4*)(B + (long)bk * ldb + bc);
    STORE_A(0)
    *(float4*)&Bs[0][bk][bc] = pb0;
    __syncthreads();
    int KT = K >> 4;
    for (int kt = 0; kt < KT; kt++) {
        int cur = kt & 1, nxt = cur ^ 1;
        if (kt + 1 < KT) {
            int k0 = (kt + 1) << 4;
            pa0 = *(const float4*)(Arow + k0 + ak);
            pa1 = *(const float4*)(Arow + k0 + ak + 4);
            pb0 = *(const float4*)(B + (long)(k0 + bk) * ldb + bc);
        }
        #pragma unroll
        for (int kk = 0; kk < 16; kk++) {
            float4 x0 = *(const float4*)&As[cur][kk][ra];
            float4 y0 = *(const float4*)&Bs[cur][kk][c4];
            float4 y1 = *(const float4*)&Bs[cur][kk][c4 + 32];
            float av_[4] = {x0.x,x0.y,x0.z,x0.w};
            float bv_[8] = {y0.x,y0.y,y0.z,y0.w,y1.x,y1.y,y1.z,y1.w};
            #pragma unroll
            for (int i = 0; i < 4; i++)
                #pragma unroll
                for (int j = 0; j < 8; j++) acc[i][j] += av_[i] * bv_[j];
        }
        if (kt + 1 < KT) {
            if (nxt == 0) { STORE_A(0) } else { STORE_A(1) }
            *(float4*)&Bs[nxt][bk][bc] = pb0;
            __syncthreads();
        }
    }
    #pragma unroll
    for (int i = 0; i < 4; i++) {
        int grow = row0 + ra + i;
        float4 v0, v1;
        v0.x = scale*acc[i][0]; v0.y = scale*acc[i][1]; v0.z = scale*acc[i][2]; v0.w = scale*acc[i][3];
        v1.x = scale*acc[i][4]; v1.y = scale*acc[i][5]; v1.z = scale*acc[i][6]; v1.w = scale*acc[i][7];
        *(float4*)(C + (long)grow * 64 + c4)      = v0;
        *(float4*)(C + (long)grow * 64 + c4 + 32) = v1;
    }
}

// split-K reduce for av
__global__ void avreduce_kernel(const float* __restrict__ p, float* __restrict__ o) {
    long idx = (long)blockIdx.x * 256 + threadIdx.x;
    long bh = idx >> 14;
    long t = idx & 16383;
    float s = 0.f;
    #pragma unroll
    for (int c = 0; c < 8; c++) s += p[((bh * 8 + c) << 14) + t];
    o[idx] = s;
}

// ---------------- landmarks ----------------
__global__ void landmark_kernel(const float* __restrict__ q, const float* __restrict__ k,
                                float* __restrict__ ql, float* __restrict__ kl) {
    long idx = (long)blockIdx.x * 256 + threadIdx.x;
    int d = idx & 63;
    int m = (idx >> 6) & (MM - 1);
    long bh = idx >> 14;
    long base = ((bh * NN + (long)m * 16) << 6) + d;
    float sq = 0.f, sk = 0.f;
    #pragma unroll
    for (int j = 0; j < 16; j++) { sq += q[base + (long)j * 64]; sk += k[base + (long)j * 64]; }
    ql[idx] = sq * (1.f / 16.f);
    kl[idx] = sk * (1.f / 16.f);
}

// ---------------- softmax ----------------
template <int CNT>
__global__ void softmax_rows(float* __restrict__ X) {
    __shared__ float sh[8];
    long row = blockIdx.x;
    float* xr = X + row * (long)(CNT * 256);
    float loc[CNT];
    float mx = -3.4e38f;
    #pragma unroll
    for (int i = 0; i < CNT; i++) { loc[i] = xr[threadIdx.x + i * 256]; mx = fmaxf(mx, loc[i]); }
    mx = blockReduceMax256(mx, sh);
    float s = 0.f;
    #pragma unroll
    for (int i = 0; i < CNT; i++) { loc[i] = expf(loc[i] - mx); s += loc[i]; }
    s = blockReduceSum256(s, sh);
    float inv = 1.f / s;
    #pragma unroll
    for (int i = 0; i < CNT; i++) xr[threadIdx.x + i * 256] = loc[i] * inv;
}

// ---------------- pinv init ----------------
__global__ void scal_init_kernel() { g_scalbits[0] = 0; g_scalbits[1] = 0; }

__global__ void colmax_kernel(const float* __restrict__ a2) {
    __shared__ float sh[8];
    long row = blockIdx.x;
    float v = fabsf(a2[row * MM + threadIdx.x]);
    v = blockReduceSum256(v, sh);
    if (threadIdx.x == 0) atomicMax(&g_scalbits[0], __float_as_int(v));
}
__global__ void rowmax_kernel(const float* __restrict__ a2) {
    __shared__ float sh[8];
    long col = blockIdx.x;
    long bh = col >> 8; int j = col & (MM - 1);
    float v = fabsf(a2[(bh << 16) + (long)threadIdx.x * MM + j]);
    v = blockReduceSum256(v, sh);
    if (threadIdx.x == 0) atomicMax(&g_scalbits[1], __float_as_int(v));
}
__global__ void zinit_kernel(const float* __restrict__ a2, float* __restrict__ z) {
    long idx = (long)blockIdx.x * 256 + threadIdx.x;
    float denom = __int_as_float(g_scalbits[0]) * __int_as_float(g_scalbits[1]);
    long bh = idx >> 16; int i = (idx >> 8) & 255, j = idx & 255;
    z[idx] = a2[(bh << 16) + (long)j * MM + i] / denom;
}

// ---------------- depthwise conv: outh += conv(v) ----------------
__global__ void conv_kernel(const float* __restrict__ v, const float* __restrict__ w,
                            float* __restrict__ outh) {
    long idx = (long)blockIdx.x * 256 + threadIdx.x;
    int d = idx & 63;
    int n = (idx >> 6) & (NN - 1);
    long bh = idx >> 18;
    int h = (int)(bh & 7);
    const float* vb = v + ((bh * NN) << 6) + d;
    float s = 0.f;
    #pragma unroll
    for (int kk = 0; kk < KK; kk++) {
        int nn = n + kk - KK / 2;
        if (nn >= 0 && nn < NN) s += w[h * KK + kk] * vb[(long)nn * 64];
    }
    outh[idx] += s;
}

// ---------------- repack [B,H,N,D] -> [B,N,H*D] ----------------
__global__ void repack_kernel(const float* __restrict__ outh, float* __restrict__ rep) {
    long idx = (long)blockIdx.x * 256 + threadIdx.x;
    int c = idx & (INNER - 1);
    long r = idx >> 9;
    int h = c >> 6, d = c & 63;
    long bb = r >> 12, nn = r & (NN - 1);
    rep[idx] = outh[(((bb * HH + h) * NN + nn) << 6) + d];
}

// ---------------- host ----------------
static inline void* sym(const void* s) { void* p = nullptr; cudaGetSymbolAddress(&p, s); return p; }

extern "C" void kernel_launch(void* const* d_in, const int* in_sizes, int n_in,
                              void* d_out, int out_size) {
    const float* x    = (const float*)d_in[0];
    const float* nw   = (const float*)d_in[1];
    const float* nb   = (const float*)d_in[2];
    const float* wqkv = (const float*)d_in[3];
    const float* wout = (const float*)d_in[4];
    const float* bout = (const float*)d_in[5];
    const float* resw = (const float*)d_in[6];
    float* out = (float*)d_out;

    float* xn   = (float*)sym(g_xn);
    float* q    = (float*)sym(g_q);
    float* k    = (float*)sym(g_k);
    float* v    = (float*)sym(g_v);
    float* ql   = (float*)sym(g_ql);
    float* kl   = (float*)sym(g_kl);
    float* sim1 = (float*)sym(g_sim1);
    float* sim3 = (float*)sym(g_sim3);
    float* a2   = (float*)sym(g_a2);
    float* z    = (float*)sym(g_z);
    float* z2   = (float*)sym(g_z2);
    float* xz   = (float*)sym(g_xz);
    float* w1   = (float*)sym(g_w1);
    float* w2   = (float*)sym(g_w2);
    float* w3   = (float*)sym(g_w3);
    float* avp  = (float*)sym(g_avp);
    float* av   = (float*)sym(g_av);
    float* zav  = (float*)sym(g_zav);
    float* outh = (float*)sym(g_outh);
    float* rep  = (float*)sym(g_rep);

    const long sMM = (long)MM * MM;

    // 1. LayerNorm
    ln_kernel<<<BB * NN, 256>>>(x, nw, nb, xn);

    // 2. QKV projection
    gemm_qkv<<<dim3(12, 128, 1), 256>>>(xn, wqkv, q, k, v);

    // 3. Landmarks
    landmark_kernel<<<(BH * MM * DHD) / 256, 256>>>(q, k, ql, kl);

    // 4. Similarities (NT form)
    gemm_w<1><<<dim3(2, 32, BH), 256>>>(q, kl, sim1, nullptr, DHD, DHD, DHD, MM,
        (long)NN * DHD, (long)MM * DHD, (long)NN * MM, 0.f, 1.f, 0.f, nullptr, nullptr);
    gemm_w<1><<<dim3(2, 2, BH), 256>>>(ql, kl, a2, nullptr, DHD, DHD, DHD, MM,
        (long)MM * DHD, (long)MM * DHD, sMM, 0.f, 1.f, 0.f, nullptr, nullptr);
    gemm_w<1><<<dim3(32, 2, BH), 256>>>(ql, k, sim3, nullptr, DHD, DHD, DHD, NN,
        (long)MM * DHD, (long)NN * DHD, (long)MM * NN, 0.f, 1.f, 0.f, nullptr, nullptr);

    // 5. Softmaxes
    softmax_rows<1><<<BH * NN, 256>>>(sim1);
    softmax_rows<1><<<BH * MM, 256>>>(a2);
    softmax_rows<16><<<BH * MM, 256>>>(sim3);

    // 6. pinv init
    scal_init_kernel<<<1, 1>>>();
    colmax_kernel<<<BH * MM, 256>>>(a2);
    rowmax_kernel<<<BH * MM, 256>>>(a2);
    zinit_kernel<<<(BH * MM * MM) / 256, 256>>>(a2, z);

    // 7. Newton-Schulz (w1 = 7I - xz fused into first GEMM)
    dim3 gmm(2, 2, BH);
    for (int it = 0; it < ITERS; it++) {
        float* zin  = (it & 1) ? z2 : z;
        float* zout = (it & 1) ? z  : z2;
        gemm_w<0><<<gmm, 256>>>(a2, zin, xz, w1, MM, MM, MM, MM, sMM, sMM, sMM,
                                0.f, 1.f, 7.f, nullptr, nullptr);
        gemm_w<0><<<gmm, 256>>>(xz, w1, w2, nullptr, MM, MM, MM, MM, sMM, sMM, sMM,
                                15.f, -1.f, 0.f, nullptr, nullptr);
        gemm_w<0><<<gmm, 256>>>(xz, w2, w3, nullptr, MM, MM, MM, MM, sMM, sMM, sMM,
                                13.f, -1.f, 0.f, nullptr, nullptr);
        gemm_w<0><<<gmm, 256>>>(zin, w3, zout, nullptr, MM, MM, MM, MM, sMM, sMM, sMM,
                                0.f, 0.25f, 0.f, nullptr, nullptr);
    }
    // result in z (even ITERS)

    // 8. out = a1 @ (z @ (a3 @ v))
    gemm_n<<<dim3(1, 2, BH * 8), 256>>>(sim3, v, avp, 512, NN, DHD,
        (long)MM * NN, (long)NN * DHD, (long)MM * DHD, 8, 512L, 512L * DHD, 1.f);
    avreduce_kernel<<<(BH * MM * DHD) / 256, 256>>>(avp, av);
    gemm_n<<<dim3(1, 2, BH), 256>>>(z, av, zav, MM, MM, DHD,
        sMM, (long)MM * DHD, (long)MM * DHD, 1, 0L, 0L, 1.f);
    gemm_n<<<dim3(1, 32, BH), 256>>>(sim1, zav, outh, MM, MM, DHD,
        (long)NN * MM, (long)MM * DHD, (long)NN * DHD, 1, 0L, 0L, 1.f);

    // 9. residual depthwise conv
    conv_kernel<<<(BH * NN * DHD) / 256, 256>>>(v, resw, outh);

    // 10. repack
    repack_kernel<<<(BB * NN * INNER) / 256, 256>>>(outh, rep);

    // 11. out projection + bias + residual
    gemm_w<0><<<dim3(4, 128, 1), 256>>>(rep, wout, out, nullptr, INNER, INNER, DIM, DIM,
        0L, 0L, 0L, 0.f, 1.f, 0.f, bout, x);

    (void)in_sizes; (void)n_in; (void)out_size;
}